// round 12
// baseline (speedup 1.0000x reference)
#include <cuda_runtime.h>
#include <cuda_fp16.h>
#include <cstdint>

// Problem constants (fixed by setup_inputs)
#define NBATCH 2
#define NHEAD  12
#define NH_TOT 24
#define T_SEQ  8192
#define D      64
#define G      64
#define HALF   64
#define NLOC   192          // local window keys
#define NK     256          // 192 local + 64 global
#define NB     128          // blocks per (n,h)
#define NCH    4            // key chunks
#define CHK    64           // keys per chunk

// ---- persistent preprocessed fp16 arrays (zero-init BSS, no allocs) ----
__device__ __half KHbuf[(size_t)NH_TOT * T_SEQ * D];
__device__ __half VHbuf[(size_t)NH_TOT * T_SEQ * D];
__device__ __half GKHbuf[NH_TOT * G * D];
__device__ __half GVHbuf[NH_TOT * G * D];

// All fp16 tiles: 64 cols = 128 B/row, SW128 XOR swizzle.
// smem layout: Q (single fp16) + 2 chunk buffers (K 8KB + V 8KB per buffer)
#define OFF_QH   0          // 8192: Q/8 fp16
#define OFF_BUF  8192       // 2 x (K 8192 + V 8192)
#define BUF_STRIDE 16384
#define V_OFF    8192
#define OFF_MASK 40960      // 256 floats
#define OFF_RSUM 41984      // 64*2 floats
#define SMEM_BYTES 42496    // 4 CTAs x 42.5KB = 170KB <= 227KB carveout

// O-reduce buffer overlays Q + buffers (all dead in epilogue), stride 66
#define OBS 66

__device__ __forceinline__ uint32_t sw128(uint32_t x) {   // byte-offset swizzle
    return x ^ ((x >> 3) & 0x70);
}

__device__ __forceinline__ void mma_f16(float* c, const unsigned* a, unsigned b0, unsigned b1) {
    asm volatile(
        "mma.sync.aligned.m16n8k16.row.col.f32.f16.f16.f32 "
        "{%0,%1,%2,%3}, {%4,%5,%6,%7}, {%8,%9}, {%0,%1,%2,%3};"
        : "+f"(c[0]), "+f"(c[1]), "+f"(c[2]), "+f"(c[3])
        : "r"(a[0]), "r"(a[1]), "r"(a[2]), "r"(a[3]), "r"(b0), "r"(b1));
}

__device__ __forceinline__ void ldsm_x4(unsigned& r0, unsigned& r1, unsigned& r2, unsigned& r3,
                                        uint32_t addr) {
    asm volatile("ldmatrix.sync.aligned.m8n8.x4.shared.b16 {%0,%1,%2,%3}, [%4];"
                 : "=r"(r0), "=r"(r1), "=r"(r2), "=r"(r3) : "r"(addr));
}

__device__ __forceinline__ void ldsm_x4_t(unsigned& r0, unsigned& r1, unsigned& r2, unsigned& r3,
                                          uint32_t addr) {
    asm volatile("ldmatrix.sync.aligned.m8n8.x4.trans.shared.b16 {%0,%1,%2,%3}, [%4];"
                 : "=r"(r0), "=r"(r1), "=r"(r2), "=r"(r3) : "r"(addr));
}

#define CP_ASYNC16(dst, src, sz) \
    asm volatile("cp.async.cg.shared.global [%0], [%1], 16, %2;" \
                 :: "r"(dst), "l"(src), "r"(sz) : "memory")
#define CP_COMMIT() asm volatile("cp.async.commit_group;" ::: "memory")
#define CP_WAIT0()  asm volatile("cp.async.wait_group 0;" ::: "memory")

__device__ __forceinline__ unsigned pack2h(__half x, __half y) {
    return (unsigned)__half_as_ushort(x) | ((unsigned)__half_as_ushort(y) << 16);
}

// convert 4 floats -> 4 fp16 packed in uint2
__device__ __forceinline__ uint2 cvt4h(float4 x) {
    uint2 u;
    u.x = pack2h(__float2half_rn(x.x), __float2half_rn(x.y));
    u.y = pack2h(__float2half_rn(x.z), __float2half_rn(x.w));
    return u;
}

// ================= preprocessing: fp32 K/V -> fp16 =================
#define MAIN4 ((size_t)NH_TOT * T_SEQ * 16)     // float4s in K (== V)
#define G4    ((size_t)NH_TOT * G * 16)

__global__ void __launch_bounds__(256)
prep_kernel(const float* __restrict__ kg, const float* __restrict__ vg,
            const float* __restrict__ gk, const float* __restrict__ gv)
{
    size_t idx = (size_t)blockIdx.x * 256 + threadIdx.x;
    if (idx < MAIN4) {
        float4 xk = reinterpret_cast<const float4*>(kg)[idx];
        float4 xv = reinterpret_cast<const float4*>(vg)[idx];
        reinterpret_cast<uint2*>(KHbuf)[idx] = cvt4h(xk);
        reinterpret_cast<uint2*>(VHbuf)[idx] = cvt4h(xv);
    } else if (idx < MAIN4 + G4) {
        size_t j = idx - MAIN4;
        float4 xk = reinterpret_cast<const float4*>(gk)[j];
        float4 xv = reinterpret_cast<const float4*>(gv)[j];
        reinterpret_cast<uint2*>(GKHbuf)[j] = cvt4h(xk);
        reinterpret_cast<uint2*>(GVHbuf)[j] = cvt4h(xv);
    }
}

// ================= main attention kernel =================
__global__ void __launch_bounds__(256, 4)
bla_kernel(const float* __restrict__ qg, const float* __restrict__ am,
           const float* __restrict__ gmk, float* __restrict__ out)
{
    extern __shared__ char smem[];
    float* maskv = reinterpret_cast<float*>(smem + OFF_MASK);
    float* Rsum  = reinterpret_cast<float*>(smem + OFF_RSUM);
    float* Obuf  = reinterpret_cast<float*>(smem);   // overlays Q + buffers in epilogue

    const int b = blockIdx.x;
    const int h = blockIdx.y;
    const int n = blockIdx.z;
    const int nh = n * NHEAD + h;
    const int tid = threadIdx.x;
    const int kr0 = b * HALF - HALF;

    const uint32_t smb = (uint32_t)__cvta_generic_to_shared(smem);
    const uint32_t sQh = smb + OFF_QH;

    // global fp16 row bases (128 B per row)
    const char* KHb = reinterpret_cast<const char*>(KHbuf) + (size_t)nh * T_SEQ * 128;
    const char* VHb = reinterpret_cast<const char*>(VHbuf) + (size_t)nh * T_SEQ * 128;
    const char* GKHb = reinterpret_cast<const char*>(GKHbuf) + (size_t)nh * G * 128;
    const char* GVHb = reinterpret_cast<const char*>(GVHbuf) + (size_t)nh * G * 128;

    // per-thread cp.async slots: rows (tid>>3) and (tid>>3)+32, 16B segment tid&7
    const int ld_j   = tid >> 3;
    const int ld_c16 = tid & 7;

    // issue chunk-load for chunk cc into buffer parity p
    auto issue_chunk = [&](int cc, int p) {
        const uint32_t base = smb + OFF_BUF + p * BUF_STRIDE;
        #pragma unroll
        for (int half = 0; half < 2; half++) {
            const int j = ld_j + half * 32;
            const uint32_t dst = base + sw128((uint32_t)(j * 128 + ld_c16 * 16));
            int jj = cc * CHK + j;
            const char *skh, *svh;
            unsigned sz = 16;
            if (jj < NLOC) {
                int kr = kr0 + jj;
                bool valid = (kr >= 0) && (kr < T_SEQ);
                size_t off = (size_t)(valid ? kr : 0) * 128 + ld_c16 * 16;
                sz = valid ? 16u : 0u;
                skh = KHb + off; svh = VHb + off;
            } else {
                size_t off = (size_t)(jj - NLOC) * 128 + ld_c16 * 16;
                skh = GKHb + off; svh = GVHb + off;
            }
            CP_ASYNC16(dst,         skh, sz);
            CP_ASYNC16(dst + V_OFF, svh, sz);
        }
        CP_COMMIT();
    };

    // prologue: start chunk 0 fetch immediately
    issue_chunk(0, 0);

    // ---- load Q (64x64), pre-scale by 1/8, single fp16, swizzled ----
    const float4* q4 = reinterpret_cast<const float4*>(qg + ((size_t)nh * T_SEQ + (size_t)b * HALF) * D);
    for (int i = tid; i < 64 * 16; i += 256) {
        int r = i >> 4, c4 = i & 15;
        float4 x = q4[i];
        x.x *= 0.125f; x.y *= 0.125f; x.z *= 0.125f; x.w *= 0.125f;
        uint32_t s = sw128((uint32_t)(r * 128 + c4 * 8));
        *reinterpret_cast<uint2*>(smem + OFF_QH + s) = cvt4h(x);
    }
    // ---- mask values per key (256 threads == NK) ----
    {
        int j = tid;
        float mval;
        if (j < NLOC) {
            int kr = kr0 + j;
            mval = (kr >= 0 && kr < T_SEQ) ? am[n * T_SEQ + kr] : -10000.0f;
        } else {
            mval = gmk[n * G + (j - NLOC)];
        }
        maskv[j] = mval;
    }

    // ---- warp tiling: 8 warps = 4 (M, 16 rows) x 2 (key halves of 32 per chunk) ----
    const int lane = tid & 31;
    const int warp = tid >> 5;
    const int wm = warp >> 1;
    const int kg2 = warp & 1;
    const int gr = lane >> 2;
    const int tig = lane & 3;
    const int row0 = wm * 16;

    // ldmatrix per-lane offset components
    const int a_row  = (lane & 15);
    const int a_seg  = (lane >> 4) * 16;                  // bytes
    const int b_nrow = (lane & 7) + ((lane >> 4) << 3);
    const int b_seg  = (lane & 8) ? 16 : 0;               // bytes
    const int v_krow = (lane & 7) + (lane & 8);
    const int v_seg  = (lane >> 4) * 16;                  // bytes

    // persistent accumulators
    float acc2[8][4];
    #pragma unroll
    for (int i = 0; i < 8; i++) {
        acc2[i][0] = 0.f; acc2[i][1] = 0.f; acc2[i][2] = 0.f; acc2[i][3] = 0.f;
    }
    float rs0 = 0.f, rs1 = 0.f;

    // ================= stream keys: 4 chunks of 64, double-buffered =================
    for (int c = 0; c < NCH; c++) {
        const int p = c & 1;
        const uint32_t sKH = smb + OFF_BUF + p * BUF_STRIDE;
        const uint32_t sVH = sKH + V_OFF;

        CP_WAIT0();          // chunk c landed (the only pending group)
        __syncthreads();     // visible to all; prev chunk's buffer fully consumed

        if (c + 1 < NCH) issue_chunk(c + 1, p ^ 1);   // overlaps compute below

        // ---- GEMM1 chunk: S[16 x 32] per warp, Q and K single fp16 ----
        float acc[4][4];
        #pragma unroll
        for (int i = 0; i < 4; i++) {
            acc[i][0]=0.f; acc[i][1]=0.f; acc[i][2]=0.f; acc[i][3]=0.f;
        }
        #pragma unroll
        for (int kt = 0; kt < 4; kt++) {
            unsigned qh[4];
            const uint32_t qoff = sw128((uint32_t)((row0 + a_row) * 128 + kt * 32 + a_seg));
            ldsm_x4(qh[0], qh[1], qh[2], qh[3], sQh + qoff);
            #pragma unroll
            for (int s = 0; s < 2; s++) {
                const uint32_t koff = sw128((uint32_t)((kg2 * 32 + s * 16 + b_nrow) * 128 + kt * 32 + b_seg));
                unsigned bh[4];
                ldsm_x4(bh[0], bh[1], bh[2], bh[3], sKH + koff);
                mma_f16(acc[2*s],   qh, bh[0], bh[1]);
                mma_f16(acc[2*s+1], qh, bh[2], bh[3]);
            }
        }

        // ---- softmax chunk (no max subtraction; masks handle pads; Q pre-scaled) ----
        unsigned pe[4][2];   // P hi only (fp16)
        #pragma unroll
        for (int nt = 0; nt < 4; nt++) {
            int kidx = c * CHK + kg2 * 32 + nt * 8 + tig * 2;
            float m0 = maskv[kidx], m1 = maskv[kidx + 1];
            float e0 = __expf(acc[nt][0] + m0);
            float e1 = __expf(acc[nt][1] + m1);
            float e2 = __expf(acc[nt][2] + m0);
            float e3 = __expf(acc[nt][3] + m1);
            rs0 += e0 + e1;
            rs1 += e2 + e3;
            pe[nt][0] = pack2h(__float2half_rn(e0), __float2half_rn(e1));
            pe[nt][1] = pack2h(__float2half_rn(e2), __float2half_rn(e3));
        }

        // ---- GEMM2 chunk: accumulate O_partial over own 32 keys (P single fp16) ----
        #pragma unroll
        for (int s = 0; s < 2; s++) {
            unsigned ah[4] = { pe[2*s][0], pe[2*s][1], pe[2*s+1][0], pe[2*s+1][1] };
            #pragma unroll
            for (int pp = 0; pp < 4; pp++) {
                const uint32_t voff = sw128((uint32_t)((kg2 * 32 + s * 16 + v_krow) * 128 + pp * 32 + v_seg));
                unsigned bh[4];
                ldsm_x4_t(bh[0], bh[1], bh[2], bh[3], sVH + voff);
                mma_f16(acc2[2*pp],   ah, bh[0], bh[1]);
                mma_f16(acc2[2*pp+1], ah, bh[2], bh[3]);
            }
        }
    }

    // ---- row-sum reduce ----
    rs0 += __shfl_xor_sync(0xffffffffu, rs0, 1);
    rs0 += __shfl_xor_sync(0xffffffffu, rs0, 2);
    rs1 += __shfl_xor_sync(0xffffffffu, rs1, 1);
    rs1 += __shfl_xor_sync(0xffffffffu, rs1, 2);
    if (tig == 0) {
        Rsum[(row0 + gr) * 2 + kg2]     = rs0;
        Rsum[(row0 + gr + 8) * 2 + kg2] = rs1;
    }
    __syncthreads();   // all GEMM2 done (Q + chunk buffers dead) + Rsum visible

    // ---- cross-warp O reduce (kg=1 stages partials over dead Q/buffer region) ----
    if (kg2 == 1) {
        #pragma unroll
        for (int nt = 0; nt < 8; nt++) {
            int cc = nt * 8 + tig * 2;
            *reinterpret_cast<float2*>(Obuf + (row0 + gr) * OBS + cc)     = make_float2(acc2[nt][0], acc2[nt][1]);
            *reinterpret_cast<float2*>(Obuf + (row0 + gr + 8) * OBS + cc) = make_float2(acc2[nt][2], acc2[nt][3]);
        }
    }
    __syncthreads();
    if (kg2 == 0) {
        const float inv0 = 1.0f / (Rsum[(row0+gr)*2]   + Rsum[(row0+gr)*2+1]);
        const float inv1 = 1.0f / (Rsum[(row0+gr+8)*2] + Rsum[(row0+gr+8)*2+1]);
        float* obase = out + ((size_t)nh * T_SEQ + (size_t)b * HALF) * D;
        #pragma unroll
        for (int nt = 0; nt < 8; nt++) {
            int cc = nt * 8 + tig * 2;
            float2 p0 = *reinterpret_cast<float2*>(Obuf + (row0 + gr) * OBS + cc);
            float2 p1 = *reinterpret_cast<float2*>(Obuf + (row0 + gr + 8) * OBS + cc);
            float2 o0 = make_float2((acc2[nt][0] + p0.x) * inv0, (acc2[nt][1] + p0.y) * inv0);
            float2 o1 = make_float2((acc2[nt][2] + p1.x) * inv1, (acc2[nt][3] + p1.y) * inv1);
            *reinterpret_cast<float2*>(obase + (row0 + gr) * D + cc)     = o0;
            *reinterpret_cast<float2*>(obase + (row0 + gr + 8) * D + cc) = o1;
        }
    }
}

extern "C" void kernel_launch(void* const* d_in, const int* in_sizes, int n_in,
                              void* d_out, int out_size) {
    const float* q   = (const float*)d_in[0];
    const float* k   = (const float*)d_in[1];
    const float* v   = (const float*)d_in[2];
    const float* am  = (const float*)d_in[3];
    const float* gk  = (const float*)d_in[4];
    const float* gv  = (const float*)d_in[5];
    const float* gmk = (const float*)d_in[6];
    float* out = (float*)d_out;

    // preprocessing: convert K/V to fp16 persistent arrays
    const size_t total4 = MAIN4 + G4;
    const int pgrid = (int)((total4 + 255) / 256);
    prep_kernel<<<pgrid, 256>>>(k, v, gk, gv);

    cudaFuncSetAttribute(bla_kernel, cudaFuncAttributeMaxDynamicSharedMemorySize, SMEM_BYTES);
    dim3 grid(NB, NHEAD, NBATCH);   // b fastest -> adjacent CTAs share K/V window in L2
    bla_kernel<<<grid, 256, SMEM_BYTES>>>(q, am, gmk, out);
}

// round 13
// speedup vs baseline: 1.1325x; 1.1325x over previous
#include <cuda_runtime.h>
#include <cuda_fp16.h>
#include <cstdint>

// Problem constants (fixed by setup_inputs)
#define NBATCH 2
#define NHEAD  12
#define NH_TOT 24
#define T_SEQ  8192
#define D      64
#define G      64
#define HALF   64
#define NLOC   192          // local window keys
#define NK     256          // 192 local + 64 global
#define NB     128          // blocks per (n,h)
#define NCH    8            // key chunks
#define CHK    32           // keys per chunk

// ---- persistent preprocessed fp16 arrays (zero-init BSS, no allocs) ----
__device__ __half KHbuf[(size_t)NH_TOT * T_SEQ * D];
__device__ __half VHbuf[(size_t)NH_TOT * T_SEQ * D];
__device__ __half GKHbuf[NH_TOT * G * D];
__device__ __half GVHbuf[NH_TOT * G * D];

// All fp16 tiles: 64 cols = 128 B/row, SW128 XOR swizzle.
// smem layout: Q (single fp16) + 3 chunk buffers (K 4KB + V 4KB per buffer)
#define OFF_QH   0          // 8192: Q/8 fp16
#define OFF_BUF  8192       // 3 x (K 4096 + V 4096)
#define BUF_STRIDE 8192
#define V_OFF    4096
#define OFF_MASK 32768      // 256 floats
#define OFF_RSUM 33792      // 64*2 floats
#define SMEM_BYTES 34304    // 4 CTAs x 33.5KB = 134KB, plenty of L1D left

// O-reduce buffer overlays Q + buffers (all dead in epilogue), stride 66
#define OBS 66

__device__ __forceinline__ uint32_t sw128(uint32_t x) {   // byte-offset swizzle
    return x ^ ((x >> 3) & 0x70);
}

__device__ __forceinline__ void mma_f16(float* c, const unsigned* a, unsigned b0, unsigned b1) {
    asm volatile(
        "mma.sync.aligned.m16n8k16.row.col.f32.f16.f16.f32 "
        "{%0,%1,%2,%3}, {%4,%5,%6,%7}, {%8,%9}, {%0,%1,%2,%3};"
        : "+f"(c[0]), "+f"(c[1]), "+f"(c[2]), "+f"(c[3])
        : "r"(a[0]), "r"(a[1]), "r"(a[2]), "r"(a[3]), "r"(b0), "r"(b1));
}

__device__ __forceinline__ void ldsm_x4(unsigned& r0, unsigned& r1, unsigned& r2, unsigned& r3,
                                        uint32_t addr) {
    asm volatile("ldmatrix.sync.aligned.m8n8.x4.shared.b16 {%0,%1,%2,%3}, [%4];"
                 : "=r"(r0), "=r"(r1), "=r"(r2), "=r"(r3) : "r"(addr));
}

__device__ __forceinline__ void ldsm_x4_t(unsigned& r0, unsigned& r1, unsigned& r2, unsigned& r3,
                                          uint32_t addr) {
    asm volatile("ldmatrix.sync.aligned.m8n8.x4.trans.shared.b16 {%0,%1,%2,%3}, [%4];"
                 : "=r"(r0), "=r"(r1), "=r"(r2), "=r"(r3) : "r"(addr));
}

#define CP_ASYNC16(dst, src, sz) \
    asm volatile("cp.async.cg.shared.global [%0], [%1], 16, %2;" \
                 :: "r"(dst), "l"(src), "r"(sz) : "memory")
#define CP_COMMIT() asm volatile("cp.async.commit_group;" ::: "memory")
#define CP_WAIT1()  asm volatile("cp.async.wait_group 1;" ::: "memory")

__device__ __forceinline__ unsigned pack2h(__half x, __half y) {
    return (unsigned)__half_as_ushort(x) | ((unsigned)__half_as_ushort(y) << 16);
}

// convert 4 floats -> 4 fp16 packed in uint2
__device__ __forceinline__ uint2 cvt4h(float4 x) {
    uint2 u;
    u.x = pack2h(__float2half_rn(x.x), __float2half_rn(x.y));
    u.y = pack2h(__float2half_rn(x.z), __float2half_rn(x.w));
    return u;
}

// ================= preprocessing: fp32 K/V -> fp16 =================
#define MAIN4 ((size_t)NH_TOT * T_SEQ * 16)     // float4s in K (== V)
#define G4    ((size_t)NH_TOT * G * 16)

__global__ void __launch_bounds__(256)
prep_kernel(const float* __restrict__ kg, const float* __restrict__ vg,
            const float* __restrict__ gk, const float* __restrict__ gv)
{
    size_t idx = (size_t)blockIdx.x * 256 + threadIdx.x;
    if (idx < MAIN4) {
        float4 xk = reinterpret_cast<const float4*>(kg)[idx];
        float4 xv = reinterpret_cast<const float4*>(vg)[idx];
        reinterpret_cast<uint2*>(KHbuf)[idx] = cvt4h(xk);
        reinterpret_cast<uint2*>(VHbuf)[idx] = cvt4h(xv);
    } else if (idx < MAIN4 + G4) {
        size_t j = idx - MAIN4;
        float4 xk = reinterpret_cast<const float4*>(gk)[j];
        float4 xv = reinterpret_cast<const float4*>(gv)[j];
        reinterpret_cast<uint2*>(GKHbuf)[j] = cvt4h(xk);
        reinterpret_cast<uint2*>(GVHbuf)[j] = cvt4h(xv);
    }
}

// ================= main attention kernel =================
__global__ void __launch_bounds__(256, 4)
bla_kernel(const float* __restrict__ qg, const float* __restrict__ am,
           const float* __restrict__ gmk, float* __restrict__ out)
{
    extern __shared__ char smem[];
    float* maskv = reinterpret_cast<float*>(smem + OFF_MASK);
    float* Rsum  = reinterpret_cast<float*>(smem + OFF_RSUM);
    float* Obuf  = reinterpret_cast<float*>(smem);   // overlays Q + buffers in epilogue

    const int b = blockIdx.x;
    const int h = blockIdx.y;
    const int n = blockIdx.z;
    const int nh = n * NHEAD + h;
    const int tid = threadIdx.x;
    const int kr0 = b * HALF - HALF;

    const uint32_t smb = (uint32_t)__cvta_generic_to_shared(smem);
    const uint32_t sQh = smb + OFF_QH;

    // global fp16 row bases (128 B per row)
    const char* KHb = reinterpret_cast<const char*>(KHbuf) + (size_t)nh * T_SEQ * 128;
    const char* VHb = reinterpret_cast<const char*>(VHbuf) + (size_t)nh * T_SEQ * 128;
    const char* GKHb = reinterpret_cast<const char*>(GKHbuf) + (size_t)nh * G * 128;
    const char* GVHb = reinterpret_cast<const char*>(GVHbuf) + (size_t)nh * G * 128;

    // per-thread cp.async slot: row j (0..31), 16B segment c16 (0..7)
    const int ld_j   = tid >> 3;
    const int ld_c16 = tid & 7;
    const uint32_t ld_dst = sw128((uint32_t)(ld_j * 128 + ld_c16 * 16));

    // issue chunk-load for chunk cc into buffer p (always commits a group)
    auto issue_chunk = [&](int cc, int p) {
        if (cc < NCH) {
            const uint32_t base = smb + OFF_BUF + p * BUF_STRIDE + ld_dst;
            int jj = cc * CHK + ld_j;
            const char *skh, *svh;
            unsigned sz = 16;
            if (jj < NLOC) {
                int kr = kr0 + jj;
                bool valid = (kr >= 0) && (kr < T_SEQ);
                size_t off = (size_t)(valid ? kr : 0) * 128 + ld_c16 * 16;
                sz = valid ? 16u : 0u;
                skh = KHb + off; svh = VHb + off;
            } else {
                size_t off = (size_t)(jj - NLOC) * 128 + ld_c16 * 16;
                skh = GKHb + off; svh = GVHb + off;
            }
            CP_ASYNC16(base,         skh, sz);
            CP_ASYNC16(base + V_OFF, svh, sz);
        }
        CP_COMMIT();   // empty group when cc >= NCH keeps wait_group accounting uniform
    };

    // prologue: start chunks 0 and 1 immediately
    issue_chunk(0, 0);
    issue_chunk(1, 1);

    // ---- load Q (64x64), pre-scale by 1/8, single fp16, swizzled ----
    const float4* q4 = reinterpret_cast<const float4*>(qg + ((size_t)nh * T_SEQ + (size_t)b * HALF) * D);
    for (int i = tid; i < 64 * 16; i += 256) {
        int r = i >> 4, c4 = i & 15;
        float4 x = q4[i];
        x.x *= 0.125f; x.y *= 0.125f; x.z *= 0.125f; x.w *= 0.125f;
        uint32_t s = sw128((uint32_t)(r * 128 + c4 * 8));
        *reinterpret_cast<uint2*>(smem + OFF_QH + s) = cvt4h(x);
    }
    // ---- mask values per key (256 threads == NK) ----
    {
        int j = tid;
        float mval;
        if (j < NLOC) {
            int kr = kr0 + j;
            mval = (kr >= 0 && kr < T_SEQ) ? am[n * T_SEQ + kr] : -10000.0f;
        } else {
            mval = gmk[n * G + (j - NLOC)];
        }
        maskv[j] = mval;
    }

    // ---- warp tiling: 8 warps = 4 (M, 16 rows) x 2 (key halves of 16 per chunk) ----
    const int lane = tid & 31;
    const int warp = tid >> 5;
    const int wm = warp >> 1;
    const int kg2 = warp & 1;
    const int gr = lane >> 2;
    const int tig = lane & 3;
    const int row0 = wm * 16;

    // ldmatrix per-lane offset components
    const int a_row  = (lane & 15);
    const int a_seg  = (lane >> 4) * 16;                  // bytes
    const int b_nrow = (lane & 7) + ((lane >> 4) << 3);
    const int b_seg  = (lane & 8) ? 16 : 0;               // bytes
    const int v_krow = (lane & 7) + (lane & 8);
    const int v_seg  = (lane >> 4) * 16;                  // bytes

    // persistent accumulators
    float acc2[8][4];
    #pragma unroll
    for (int i = 0; i < 8; i++) {
        acc2[i][0] = 0.f; acc2[i][1] = 0.f; acc2[i][2] = 0.f; acc2[i][3] = 0.f;
    }
    float rs0 = 0.f, rs1 = 0.f;

    // ================= stream keys: 8 chunks of 32, triple-buffered (depth 2) =================
    for (int c = 0; c < NCH; c++) {
        const int p = c % 3;
        const uint32_t sKH = smb + OFF_BUF + p * BUF_STRIDE;
        const uint32_t sVH = sKH + V_OFF;

        CP_WAIT1();          // pending = {c, c+1}; returns when chunk c landed
        __syncthreads();     // visible to all; buffer (c+2)%3 consumed at iter c-1

        issue_chunk(c + 2, (c + 2) % 3);   // overlaps compute below

        // ---- GEMM1 chunk: S[16 x 16] per warp, Q and K single fp16 ----
        float acc[2][4];
        acc[0][0]=0.f; acc[0][1]=0.f; acc[0][2]=0.f; acc[0][3]=0.f;
        acc[1][0]=0.f; acc[1][1]=0.f; acc[1][2]=0.f; acc[1][3]=0.f;
        #pragma unroll
        for (int kt = 0; kt < 4; kt++) {
            unsigned qh[4];
            const uint32_t qoff = sw128((uint32_t)((row0 + a_row) * 128 + kt * 32 + a_seg));
            ldsm_x4(qh[0], qh[1], qh[2], qh[3], sQh + qoff);
            const uint32_t koff = sw128((uint32_t)((kg2 * 16 + b_nrow) * 128 + kt * 32 + b_seg));
            unsigned bh[4];
            ldsm_x4(bh[0], bh[1], bh[2], bh[3], sKH + koff);
            mma_f16(acc[0], qh, bh[0], bh[1]);
            mma_f16(acc[1], qh, bh[2], bh[3]);
        }

        // ---- softmax chunk (no max subtraction; masks handle pads; Q pre-scaled) ----
        unsigned pe[2][2];   // P hi only (fp16)
        #pragma unroll
        for (int nt = 0; nt < 2; nt++) {
            int kidx = c * CHK + kg2 * 16 + nt * 8 + tig * 2;
            float m0 = maskv[kidx], m1 = maskv[kidx + 1];
            float e0 = __expf(acc[nt][0] + m0);
            float e1 = __expf(acc[nt][1] + m1);
            float e2 = __expf(acc[nt][2] + m0);
            float e3 = __expf(acc[nt][3] + m1);
            rs0 += e0 + e1;
            rs1 += e2 + e3;
            pe[nt][0] = pack2h(__float2half_rn(e0), __float2half_rn(e1));
            pe[nt][1] = pack2h(__float2half_rn(e2), __float2half_rn(e3));
        }

        // ---- GEMM2 chunk: accumulate O_partial over own 16 keys (P single fp16) ----
        unsigned ah[4] = { pe[0][0], pe[0][1], pe[1][0], pe[1][1] };
        #pragma unroll
        for (int pp = 0; pp < 4; pp++) {
            const uint32_t voff = sw128((uint32_t)((kg2 * 16 + v_krow) * 128 + pp * 32 + v_seg));
            unsigned bh[4];
            ldsm_x4_t(bh[0], bh[1], bh[2], bh[3], sVH + voff);
            mma_f16(acc2[2*pp],   ah, bh[0], bh[1]);
            mma_f16(acc2[2*pp+1], ah, bh[2], bh[3]);
        }
    }

    // ---- row-sum reduce ----
    rs0 += __shfl_xor_sync(0xffffffffu, rs0, 1);
    rs0 += __shfl_xor_sync(0xffffffffu, rs0, 2);
    rs1 += __shfl_xor_sync(0xffffffffu, rs1, 1);
    rs1 += __shfl_xor_sync(0xffffffffu, rs1, 2);
    if (tig == 0) {
        Rsum[(row0 + gr) * 2 + kg2]     = rs0;
        Rsum[(row0 + gr + 8) * 2 + kg2] = rs1;
    }
    __syncthreads();   // all GEMM2 done (Q + chunk buffers dead) + Rsum visible

    // ---- cross-warp O reduce (kg=1 stages partials over dead Q/buffer region) ----
    if (kg2 == 1) {
        #pragma unroll
        for (int nt = 0; nt < 8; nt++) {
            int cc = nt * 8 + tig * 2;
            *reinterpret_cast<float2*>(Obuf + (row0 + gr) * OBS + cc)     = make_float2(acc2[nt][0], acc2[nt][1]);
            *reinterpret_cast<float2*>(Obuf + (row0 + gr + 8) * OBS + cc) = make_float2(acc2[nt][2], acc2[nt][3]);
        }
    }
    __syncthreads();
    if (kg2 == 0) {
        const float inv0 = 1.0f / (Rsum[(row0+gr)*2]   + Rsum[(row0+gr)*2+1]);
        const float inv1 = 1.0f / (Rsum[(row0+gr+8)*2] + Rsum[(row0+gr+8)*2+1]);
        float* obase = out + ((size_t)nh * T_SEQ + (size_t)b * HALF) * D;
        #pragma unroll
        for (int nt = 0; nt < 8; nt++) {
            int cc = nt * 8 + tig * 2;
            float2 p0 = *reinterpret_cast<float2*>(Obuf + (row0 + gr) * OBS + cc);
            float2 p1 = *reinterpret_cast<float2*>(Obuf + (row0 + gr + 8) * OBS + cc);
            float2 o0 = make_float2((acc2[nt][0] + p0.x) * inv0, (acc2[nt][1] + p0.y) * inv0);
            float2 o1 = make_float2((acc2[nt][2] + p1.x) * inv1, (acc2[nt][3] + p1.y) * inv1);
            *reinterpret_cast<float2*>(obase + (row0 + gr) * D + cc)     = o0;
            *reinterpret_cast<float2*>(obase + (row0 + gr + 8) * D + cc) = o1;
        }
    }
}

extern "C" void kernel_launch(void* const* d_in, const int* in_sizes, int n_in,
                              void* d_out, int out_size) {
    const float* q   = (const float*)d_in[0];
    const float* k   = (const float*)d_in[1];
    const float* v   = (const float*)d_in[2];
    const float* am  = (const float*)d_in[3];
    const float* gk  = (const float*)d_in[4];
    const float* gv  = (const float*)d_in[5];
    const float* gmk = (const float*)d_in[6];
    float* out = (float*)d_out;

    // preprocessing: convert K/V to fp16 persistent arrays
    const size_t total4 = MAIN4 + G4;
    const int pgrid = (int)((total4 + 255) / 256);
    prep_kernel<<<pgrid, 256>>>(k, v, gk, gv);

    cudaFuncSetAttribute(bla_kernel, cudaFuncAttributeMaxDynamicSharedMemorySize, SMEM_BYTES);
    dim3 grid(NB, NHEAD, NBATCH);   // b fastest -> adjacent CTAs share K/V window in L2
    bla_kernel<<<grid, 256, SMEM_BYTES>>>(q, am, gmk, out);
}

// round 14
// speedup vs baseline: 1.1779x; 1.0401x over previous
#include <cuda_runtime.h>
#include <cuda_fp16.h>
#include <cstdint>

// Problem constants (fixed by setup_inputs)
#define NBATCH 2
#define NHEAD  12
#define NH_TOT 24
#define T_SEQ  8192
#define D      64
#define G      64
#define HALF   64
#define NLOC   192          // local window keys
#define NK     256          // 192 local + 64 global
#define NB     128          // blocks per (n,h)
#define NCH    8            // key chunks
#define CHK    32           // keys per chunk

// ---- persistent preprocessed fp16 arrays (zero-init BSS, no allocs) ----
__device__ __half KHbuf[(size_t)NH_TOT * T_SEQ * D];
__device__ __half VHbuf[(size_t)NH_TOT * T_SEQ * D];
__device__ __half GKHbuf[NH_TOT * G * D];
__device__ __half GVHbuf[NH_TOT * G * D];

// All fp16 tiles: 64 cols = 128 B/row, SW128 XOR swizzle.
// smem layout: Q (single fp16) + 3 chunk buffers (K 4KB + V 4KB per buffer)
#define OFF_QH   0          // 8192: Q/8 fp16
#define OFF_BUF  8192       // 3 x (K 4096 + V 4096)
#define BUF_STRIDE 8192
#define V_OFF    4096
#define OFF_MASK 32768      // 256 floats
#define OFF_RSUM 33792      // 64*2 floats
#define SMEM_BYTES 34304    // 3 CTAs x 33.5KB = 100KB, plenty of L1D left

// O-reduce buffer overlays Q + buffers (all dead in epilogue), stride 66
#define OBS 66

__device__ __forceinline__ uint32_t sw128(uint32_t x) {   // byte-offset swizzle
    return x ^ ((x >> 3) & 0x70);
}

__device__ __forceinline__ void mma_f16(float* c, const unsigned* a, unsigned b0, unsigned b1) {
    asm volatile(
        "mma.sync.aligned.m16n8k16.row.col.f32.f16.f16.f32 "
        "{%0,%1,%2,%3}, {%4,%5,%6,%7}, {%8,%9}, {%0,%1,%2,%3};"
        : "+f"(c[0]), "+f"(c[1]), "+f"(c[2]), "+f"(c[3])
        : "r"(a[0]), "r"(a[1]), "r"(a[2]), "r"(a[3]), "r"(b0), "r"(b1));
}

__device__ __forceinline__ void ldsm_x4(unsigned& r0, unsigned& r1, unsigned& r2, unsigned& r3,
                                        uint32_t addr) {
    asm volatile("ldmatrix.sync.aligned.m8n8.x4.shared.b16 {%0,%1,%2,%3}, [%4];"
                 : "=r"(r0), "=r"(r1), "=r"(r2), "=r"(r3) : "r"(addr));
}

__device__ __forceinline__ void ldsm_x4_t(unsigned& r0, unsigned& r1, unsigned& r2, unsigned& r3,
                                          uint32_t addr) {
    asm volatile("ldmatrix.sync.aligned.m8n8.x4.trans.shared.b16 {%0,%1,%2,%3}, [%4];"
                 : "=r"(r0), "=r"(r1), "=r"(r2), "=r"(r3) : "r"(addr));
}

#define CP_ASYNC16(dst, src, sz) \
    asm volatile("cp.async.cg.shared.global [%0], [%1], 16, %2;" \
                 :: "r"(dst), "l"(src), "r"(sz) : "memory")
#define CP_COMMIT() asm volatile("cp.async.commit_group;" ::: "memory")
#define CP_WAIT1()  asm volatile("cp.async.wait_group 1;" ::: "memory")

__device__ __forceinline__ unsigned pack2h(__half x, __half y) {
    return (unsigned)__half_as_ushort(x) | ((unsigned)__half_as_ushort(y) << 16);
}

// convert 4 floats -> 4 fp16 packed in uint2
__device__ __forceinline__ uint2 cvt4h(float4 x) {
    uint2 u;
    u.x = pack2h(__float2half_rn(x.x), __float2half_rn(x.y));
    u.y = pack2h(__float2half_rn(x.z), __float2half_rn(x.w));
    return u;
}

// ================= preprocessing: fp32 K/V -> fp16 =================
#define MAIN4 ((size_t)NH_TOT * T_SEQ * 16)     // float4s in K (== V)
#define G4    ((size_t)NH_TOT * G * 16)

__global__ void __launch_bounds__(256)
prep_kernel(const float* __restrict__ kg, const float* __restrict__ vg,
            const float* __restrict__ gk, const float* __restrict__ gv)
{
    size_t idx = (size_t)blockIdx.x * 256 + threadIdx.x;
    if (idx < MAIN4) {
        float4 xk = reinterpret_cast<const float4*>(kg)[idx];
        float4 xv = reinterpret_cast<const float4*>(vg)[idx];
        reinterpret_cast<uint2*>(KHbuf)[idx] = cvt4h(xk);
        reinterpret_cast<uint2*>(VHbuf)[idx] = cvt4h(xv);
    } else if (idx < MAIN4 + G4) {
        size_t j = idx - MAIN4;
        float4 xk = reinterpret_cast<const float4*>(gk)[j];
        float4 xv = reinterpret_cast<const float4*>(gv)[j];
        reinterpret_cast<uint2*>(GKHbuf)[j] = cvt4h(xk);
        reinterpret_cast<uint2*>(GVHbuf)[j] = cvt4h(xv);
    }
}

// ================= main attention kernel =================
__global__ void __launch_bounds__(256, 3)
bla_kernel(const float* __restrict__ qg, const float* __restrict__ am,
           const float* __restrict__ gmk, float* __restrict__ out)
{
    extern __shared__ char smem[];
    float* maskv = reinterpret_cast<float*>(smem + OFF_MASK);
    float* Rsum  = reinterpret_cast<float*>(smem + OFF_RSUM);
    float* Obuf  = reinterpret_cast<float*>(smem);   // overlays Q + buffers in epilogue

    const int b = blockIdx.x;
    const int h = blockIdx.y;
    const int n = blockIdx.z;
    const int nh = n * NHEAD + h;
    const int tid = threadIdx.x;
    const int kr0 = b * HALF - HALF;

    const uint32_t smb = (uint32_t)__cvta_generic_to_shared(smem);
    const uint32_t sQh = smb + OFF_QH;

    // global fp16 row bases (128 B per row)
    const char* KHb = reinterpret_cast<const char*>(KHbuf) + (size_t)nh * T_SEQ * 128;
    const char* VHb = reinterpret_cast<const char*>(VHbuf) + (size_t)nh * T_SEQ * 128;
    const char* GKHb = reinterpret_cast<const char*>(GKHbuf) + (size_t)nh * G * 128;
    const char* GVHb = reinterpret_cast<const char*>(GVHbuf) + (size_t)nh * G * 128;

    // per-thread cp.async slot: row j (0..31), 16B segment c16 (0..7)
    const int ld_j   = tid >> 3;
    const int ld_c16 = tid & 7;
    const uint32_t ld_dst = sw128((uint32_t)(ld_j * 128 + ld_c16 * 16));

    // issue chunk-load for chunk cc into buffer p (always commits a group)
    auto issue_chunk = [&](int cc, int p) {
        if (cc < NCH) {
            const uint32_t base = smb + OFF_BUF + p * BUF_STRIDE + ld_dst;
            int jj = cc * CHK + ld_j;
            const char *skh, *svh;
            unsigned sz = 16;
            if (jj < NLOC) {
                int kr = kr0 + jj;
                bool valid = (kr >= 0) && (kr < T_SEQ);
                size_t off = (size_t)(valid ? kr : 0) * 128 + ld_c16 * 16;
                sz = valid ? 16u : 0u;
                skh = KHb + off; svh = VHb + off;
            } else {
                size_t off = (size_t)(jj - NLOC) * 128 + ld_c16 * 16;
                skh = GKHb + off; svh = GVHb + off;
            }
            CP_ASYNC16(base,         skh, sz);
            CP_ASYNC16(base + V_OFF, svh, sz);
        }
        CP_COMMIT();   // empty group when cc >= NCH keeps wait_group accounting uniform
    };

    // prologue: start chunks 0 and 1 immediately
    issue_chunk(0, 0);
    issue_chunk(1, 1);

    // ---- load Q (64x64), pre-scale by 1/8, single fp16, swizzled ----
    const float4* q4 = reinterpret_cast<const float4*>(qg + ((size_t)nh * T_SEQ + (size_t)b * HALF) * D);
    for (int i = tid; i < 64 * 16; i += 256) {
        int r = i >> 4, c4 = i & 15;
        float4 x = q4[i];
        x.x *= 0.125f; x.y *= 0.125f; x.z *= 0.125f; x.w *= 0.125f;
        uint32_t s = sw128((uint32_t)(r * 128 + c4 * 8));
        *reinterpret_cast<uint2*>(smem + OFF_QH + s) = cvt4h(x);
    }
    // ---- mask values per key (256 threads == NK) ----
    {
        int j = tid;
        float mval;
        if (j < NLOC) {
            int kr = kr0 + j;
            mval = (kr >= 0 && kr < T_SEQ) ? am[n * T_SEQ + kr] : -10000.0f;
        } else {
            mval = gmk[n * G + (j - NLOC)];
        }
        maskv[j] = mval;
    }
    __syncthreads();   // Q + mask visible to all warps

    // ---- warp tiling: 8 warps = 4 (M, 16 rows) x 2 (key halves of 16 per chunk) ----
    const int lane = tid & 31;
    const int warp = tid >> 5;
    const int wm = warp >> 1;
    const int kg2 = warp & 1;
    const int gr = lane >> 2;
    const int tig = lane & 3;
    const int row0 = wm * 16;

    // ldmatrix per-lane offset components
    const int a_row  = (lane & 15);
    const int a_seg  = (lane >> 4) * 16;                  // bytes
    const int b_nrow = (lane & 7) + ((lane >> 4) << 3);
    const int b_seg  = (lane & 8) ? 16 : 0;               // bytes
    const int v_krow = (lane & 7) + (lane & 8);
    const int v_seg  = (lane >> 4) * 16;                  // bytes

    // ---- hoist Q fragments into registers ONCE (16 regs, reused all 8 chunks) ----
    unsigned qfrag[4][4];
    #pragma unroll
    for (int kt = 0; kt < 4; kt++) {
        const uint32_t qoff = sw128((uint32_t)((row0 + a_row) * 128 + kt * 32 + a_seg));
        ldsm_x4(qfrag[kt][0], qfrag[kt][1], qfrag[kt][2], qfrag[kt][3], sQh + qoff);
    }

    // persistent accumulators
    float acc2[8][4];
    #pragma unroll
    for (int i = 0; i < 8; i++) {
        acc2[i][0] = 0.f; acc2[i][1] = 0.f; acc2[i][2] = 0.f; acc2[i][3] = 0.f;
    }
    float rs0 = 0.f, rs1 = 0.f;

    // ================= stream keys: 8 chunks of 32, triple-buffered (depth 2) =================
    for (int c = 0; c < NCH; c++) {
        const int p = c % 3;
        const uint32_t sKH = smb + OFF_BUF + p * BUF_STRIDE;
        const uint32_t sVH = sKH + V_OFF;

        CP_WAIT1();          // pending = {c, c+1}; returns when chunk c landed
        __syncthreads();     // visible to all; buffer (c+2)%3 consumed at iter c-1

        issue_chunk(c + 2, (c + 2) % 3);   // overlaps compute below

        // ---- GEMM1 chunk: S[16 x 16] per warp, Q in regs, K single fp16 ----
        float acc[2][4];
        acc[0][0]=0.f; acc[0][1]=0.f; acc[0][2]=0.f; acc[0][3]=0.f;
        acc[1][0]=0.f; acc[1][1]=0.f; acc[1][2]=0.f; acc[1][3]=0.f;
        #pragma unroll
        for (int kt = 0; kt < 4; kt++) {
            const uint32_t koff = sw128((uint32_t)((kg2 * 16 + b_nrow) * 128 + kt * 32 + b_seg));
            unsigned bh[4];
            ldsm_x4(bh[0], bh[1], bh[2], bh[3], sKH + koff);
            mma_f16(acc[0], qfrag[kt], bh[0], bh[1]);
            mma_f16(acc[1], qfrag[kt], bh[2], bh[3]);
        }

        // ---- softmax chunk (no max subtraction; masks handle pads; Q pre-scaled) ----
        unsigned pe[2][2];   // P hi only (fp16)
        #pragma unroll
        for (int nt = 0; nt < 2; nt++) {
            int kidx = c * CHK + kg2 * 16 + nt * 8 + tig * 2;
            float m0 = maskv[kidx], m1 = maskv[kidx + 1];
            float e0 = __expf(acc[nt][0] + m0);
            float e1 = __expf(acc[nt][1] + m1);
            float e2 = __expf(acc[nt][2] + m0);
            float e3 = __expf(acc[nt][3] + m1);
            rs0 += e0 + e1;
            rs1 += e2 + e3;
            pe[nt][0] = pack2h(__float2half_rn(e0), __float2half_rn(e1));
            pe[nt][1] = pack2h(__float2half_rn(e2), __float2half_rn(e3));
        }

        // ---- GEMM2 chunk: accumulate O_partial over own 16 keys (P single fp16) ----
        unsigned ah[4] = { pe[0][0], pe[0][1], pe[1][0], pe[1][1] };
        #pragma unroll
        for (int pp = 0; pp < 4; pp++) {
            const uint32_t voff = sw128((uint32_t)((kg2 * 16 + v_krow) * 128 + pp * 32 + v_seg));
            unsigned bh[4];
            ldsm_x4_t(bh[0], bh[1], bh[2], bh[3], sVH + voff);
            mma_f16(acc2[2*pp],   ah, bh[0], bh[1]);
            mma_f16(acc2[2*pp+1], ah, bh[2], bh[3]);
        }
    }

    // ---- row-sum reduce ----
    rs0 += __shfl_xor_sync(0xffffffffu, rs0, 1);
    rs0 += __shfl_xor_sync(0xffffffffu, rs0, 2);
    rs1 += __shfl_xor_sync(0xffffffffu, rs1, 1);
    rs1 += __shfl_xor_sync(0xffffffffu, rs1, 2);
    if (tig == 0) {
        Rsum[(row0 + gr) * 2 + kg2]     = rs0;
        Rsum[(row0 + gr + 8) * 2 + kg2] = rs1;
    }
    __syncthreads();   // all GEMM2 done (Q + chunk buffers dead) + Rsum visible

    // ---- cross-warp O reduce (kg=1 stages partials over dead Q/buffer region) ----
    if (kg2 == 1) {
        #pragma unroll
        for (int nt = 0; nt < 8; nt++) {
            int cc = nt * 8 + tig * 2;
            *reinterpret_cast<float2*>(Obuf + (row0 + gr) * OBS + cc)     = make_float2(acc2[nt][0], acc2[nt][1]);
            *reinterpret_cast<float2*>(Obuf + (row0 + gr + 8) * OBS + cc) = make_float2(acc2[nt][2], acc2[nt][3]);
        }
    }
    __syncthreads();
    if (kg2 == 0) {
        const float inv0 = 1.0f / (Rsum[(row0+gr)*2]   + Rsum[(row0+gr)*2+1]);
        const float inv1 = 1.0f / (Rsum[(row0+gr+8)*2] + Rsum[(row0+gr+8)*2+1]);
        float* obase = out + ((size_t)nh * T_SEQ + (size_t)b * HALF) * D;
        #pragma unroll
        for (int nt = 0; nt < 8; nt++) {
            int cc = nt * 8 + tig * 2;
            float2 p0 = *reinterpret_cast<float2*>(Obuf + (row0 + gr) * OBS + cc);
            float2 p1 = *reinterpret_cast<float2*>(Obuf + (row0 + gr + 8) * OBS + cc);
            float2 o0 = make_float2((acc2[nt][0] + p0.x) * inv0, (acc2[nt][1] + p0.y) * inv0);
            float2 o1 = make_float2((acc2[nt][2] + p1.x) * inv1, (acc2[nt][3] + p1.y) * inv1);
            *reinterpret_cast<float2*>(obase + (row0 + gr) * D + cc)     = o0;
            *reinterpret_cast<float2*>(obase + (row0 + gr + 8) * D + cc) = o1;
        }
    }
}

extern "C" void kernel_launch(void* const* d_in, const int* in_sizes, int n_in,
                              void* d_out, int out_size) {
    const float* q   = (const float*)d_in[0];
    const float* k   = (const float*)d_in[1];
    const float* v   = (const float*)d_in[2];
    const float* am  = (const float*)d_in[3];
    const float* gk  = (const float*)d_in[4];
    const float* gv  = (const float*)d_in[5];
    const float* gmk = (const float*)d_in[6];
    float* out = (float*)d_out;

    // preprocessing: convert K/V to fp16 persistent arrays
    const size_t total4 = MAIN4 + G4;
    const int pgrid = (int)((total4 + 255) / 256);
    prep_kernel<<<pgrid, 256>>>(k, v, gk, gv);

    cudaFuncSetAttribute(bla_kernel, cudaFuncAttributeMaxDynamicSharedMemorySize, SMEM_BYTES);
    dim3 grid(NB, NHEAD, NBATCH);   // b fastest -> adjacent CTAs share K/V window in L2
    bla_kernel<<<grid, 256, SMEM_BYTES>>>(q, am, gmk, out);
}

// round 15
// speedup vs baseline: 1.2204x; 1.0361x over previous
#include <cuda_runtime.h>
#include <cuda_fp16.h>
#include <cstdint>

// Problem constants (fixed by setup_inputs)
#define NBATCH 2
#define NHEAD  12
#define NH_TOT 24
#define T_SEQ  8192
#define D      64
#define G      64
#define HALF   64
#define NLOC   192          // local window keys
#define NK     256          // 192 local + 64 global
#define NB     128          // blocks per (n,h)
#define NCH    8            // key chunks
#define CHK    32           // keys per chunk

#define LOG2E  1.44269504f

// ---- persistent preprocessed fp16 arrays (zero-init BSS, no allocs) ----
__device__ __half KHbuf[(size_t)NH_TOT * T_SEQ * D];
__device__ __half VHbuf[(size_t)NH_TOT * T_SEQ * D];
__device__ __half GKHbuf[NH_TOT * G * D];
__device__ __half GVHbuf[NH_TOT * G * D];

// All fp16 tiles: 64 cols = 128 B/row, SW128 XOR swizzle.
// smem layout: Q (single fp16) + 3 chunk buffers (K 4KB + V 4KB per buffer)
#define OFF_QH   0          // 8192: Q*log2e/8 fp16
#define OFF_BUF  8192       // 3 x (K 4096 + V 4096)
#define BUF_STRIDE 8192
#define V_OFF    4096
#define OFF_MASK 32768      // 256 floats
#define SMEM_BYTES 33792    // 6 CTAs x 33KB = 198KB <= 228KB carveout

__device__ __forceinline__ uint32_t sw128(uint32_t x) {   // byte-offset swizzle
    return x ^ ((x >> 3) & 0x70);
}

__device__ __forceinline__ void mma_f16(float* c, const unsigned* a, unsigned b0, unsigned b1) {
    asm volatile(
        "mma.sync.aligned.m16n8k16.row.col.f32.f16.f16.f32 "
        "{%0,%1,%2,%3}, {%4,%5,%6,%7}, {%8,%9}, {%0,%1,%2,%3};"
        : "+f"(c[0]), "+f"(c[1]), "+f"(c[2]), "+f"(c[3])
        : "r"(a[0]), "r"(a[1]), "r"(a[2]), "r"(a[3]), "r"(b0), "r"(b1));
}

__device__ __forceinline__ void ldsm_x4(unsigned& r0, unsigned& r1, unsigned& r2, unsigned& r3,
                                        uint32_t addr) {
    asm volatile("ldmatrix.sync.aligned.m8n8.x4.shared.b16 {%0,%1,%2,%3}, [%4];"
                 : "=r"(r0), "=r"(r1), "=r"(r2), "=r"(r3) : "r"(addr));
}

__device__ __forceinline__ void ldsm_x4_t(unsigned& r0, unsigned& r1, unsigned& r2, unsigned& r3,
                                          uint32_t addr) {
    asm volatile("ldmatrix.sync.aligned.m8n8.x4.trans.shared.b16 {%0,%1,%2,%3}, [%4];"
                 : "=r"(r0), "=r"(r1), "=r"(r2), "=r"(r3) : "r"(addr));
}

#define CP_ASYNC16(dst, src, sz) \
    asm volatile("cp.async.cg.shared.global [%0], [%1], 16, %2;" \
                 :: "r"(dst), "l"(src), "r"(sz) : "memory")
#define CP_COMMIT() asm volatile("cp.async.commit_group;" ::: "memory")
#define CP_WAIT1()  asm volatile("cp.async.wait_group 1;" ::: "memory")

__device__ __forceinline__ unsigned pack2h(__half x, __half y) {
    return (unsigned)__half_as_ushort(x) | ((unsigned)__half_as_ushort(y) << 16);
}

// convert 4 floats -> 4 fp16 packed in uint2
__device__ __forceinline__ uint2 cvt4h(float4 x) {
    uint2 u;
    u.x = pack2h(__float2half_rn(x.x), __float2half_rn(x.y));
    u.y = pack2h(__float2half_rn(x.z), __float2half_rn(x.w));
    return u;
}

// ================= preprocessing: fp32 K/V -> fp16 =================
#define MAIN4 ((size_t)NH_TOT * T_SEQ * 16)     // float4s in K (== V)
#define G4    ((size_t)NH_TOT * G * 16)

__global__ void __launch_bounds__(256)
prep_kernel(const float* __restrict__ kg, const float* __restrict__ vg,
            const float* __restrict__ gk, const float* __restrict__ gv)
{
    size_t idx = (size_t)blockIdx.x * 256 + threadIdx.x;
    if (idx < MAIN4) {
        float4 xk = reinterpret_cast<const float4*>(kg)[idx];
        float4 xv = reinterpret_cast<const float4*>(vg)[idx];
        reinterpret_cast<uint2*>(KHbuf)[idx] = cvt4h(xk);
        reinterpret_cast<uint2*>(VHbuf)[idx] = cvt4h(xv);
    } else if (idx < MAIN4 + G4) {
        size_t j = idx - MAIN4;
        float4 xk = reinterpret_cast<const float4*>(gk)[j];
        float4 xv = reinterpret_cast<const float4*>(gv)[j];
        reinterpret_cast<uint2*>(GKHbuf)[j] = cvt4h(xk);
        reinterpret_cast<uint2*>(GVHbuf)[j] = cvt4h(xv);
    }
}

// ================= main attention kernel (128 threads, 4 warps) =================
__global__ void __launch_bounds__(128, 6)
bla_kernel(const float* __restrict__ qg, const float* __restrict__ am,
           const float* __restrict__ gmk, float* __restrict__ out)
{
    extern __shared__ char smem[];
    float* maskv = reinterpret_cast<float*>(smem + OFF_MASK);

    const int b = blockIdx.x;
    const int h = blockIdx.y;
    const int n = blockIdx.z;
    const int nh = n * NHEAD + h;
    const int tid = threadIdx.x;
    const int kr0 = b * HALF - HALF;

    const uint32_t smb = (uint32_t)__cvta_generic_to_shared(smem);
    const uint32_t sQh = smb + OFF_QH;

    // global fp16 row bases (128 B per row)
    const char* KHb = reinterpret_cast<const char*>(KHbuf) + (size_t)nh * T_SEQ * 128;
    const char* VHb = reinterpret_cast<const char*>(VHbuf) + (size_t)nh * T_SEQ * 128;
    const char* GKHb = reinterpret_cast<const char*>(GKHbuf) + (size_t)nh * G * 128;
    const char* GVHb = reinterpret_cast<const char*>(GVHbuf) + (size_t)nh * G * 128;

    // per-thread cp.async slot: row j (0..31), 32B segment (tid&3)*32
    const int ld_j = tid >> 2;
    const int ld_s = (tid & 3) * 32;
    const uint32_t ld_d0 = sw128((uint32_t)(ld_j * 128 + ld_s));
    const uint32_t ld_d1 = sw128((uint32_t)(ld_j * 128 + ld_s + 16));

    // issue chunk-load for chunk cc into buffer p (always commits a group)
    auto issue_chunk = [&](int cc, int p) {
        if (cc < NCH) {
            const uint32_t base = smb + OFF_BUF + p * BUF_STRIDE;
            int jj = cc * CHK + ld_j;
            const char *skh, *svh;
            unsigned sz = 16;
            if (jj < NLOC) {
                int kr = kr0 + jj;
                bool valid = (kr >= 0) && (kr < T_SEQ);
                size_t off = (size_t)(valid ? kr : 0) * 128 + ld_s;
                sz = valid ? 16u : 0u;
                skh = KHb + off; svh = VHb + off;
            } else {
                size_t off = (size_t)(jj - NLOC) * 128 + ld_s;
                skh = GKHb + off; svh = GVHb + off;
            }
            CP_ASYNC16(base + ld_d0,         skh,      sz);
            CP_ASYNC16(base + ld_d1,         skh + 16, sz);
            CP_ASYNC16(base + ld_d0 + V_OFF, svh,      sz);
            CP_ASYNC16(base + ld_d1 + V_OFF, svh + 16, sz);
        }
        CP_COMMIT();   // empty group when cc >= NCH keeps wait_group accounting uniform
    };

    // prologue: start chunks 0 and 1 immediately
    issue_chunk(0, 0);
    issue_chunk(1, 1);

    // ---- load Q (64x64), pre-scale by log2e/8, single fp16, swizzled ----
    const float4* q4 = reinterpret_cast<const float4*>(qg + ((size_t)nh * T_SEQ + (size_t)b * HALF) * D);
    const float qscale = 0.125f * LOG2E;
    for (int i = tid; i < 64 * 16; i += 128) {
        int r = i >> 4, c4 = i & 15;
        float4 x = q4[i];
        x.x *= qscale; x.y *= qscale; x.z *= qscale; x.w *= qscale;
        uint32_t s = sw128((uint32_t)(r * 128 + c4 * 8));
        *reinterpret_cast<uint2*>(smem + OFF_QH + s) = cvt4h(x);
    }
    // ---- mask values per key, pre-scaled by log2e ----
    for (int j = tid; j < NK; j += 128) {
        float mval;
        if (j < NLOC) {
            int kr = kr0 + j;
            mval = (kr >= 0 && kr < T_SEQ) ? am[n * T_SEQ + kr] : -10000.0f;
        } else {
            mval = gmk[n * G + (j - NLOC)];
        }
        maskv[j] = mval * LOG2E;
    }
    __syncthreads();   // Q + mask visible to all warps

    // ---- warp tiling: 4 warps = 4 M-groups (16 rows), each over ALL chunk keys ----
    const int lane = tid & 31;
    const int warp = tid >> 5;
    const int gr = lane >> 2;
    const int tig = lane & 3;
    const int row0 = warp * 16;

    // ldmatrix per-lane offset components
    const int a_row  = (lane & 15);
    const int a_seg  = (lane >> 4) * 16;                  // bytes
    const int b_nrow = (lane & 7) + ((lane >> 4) << 3);
    const int b_seg  = (lane & 8) ? 16 : 0;               // bytes
    const int v_krow = (lane & 7) + (lane & 8);
    const int v_seg  = (lane >> 4) * 16;                  // bytes

    // ---- hoist Q fragments into registers ONCE (16 regs, reused all 8 chunks) ----
    unsigned qfrag[4][4];
    #pragma unroll
    for (int kt = 0; kt < 4; kt++) {
        const uint32_t qoff = sw128((uint32_t)((row0 + a_row) * 128 + kt * 32 + a_seg));
        ldsm_x4(qfrag[kt][0], qfrag[kt][1], qfrag[kt][2], qfrag[kt][3], sQh + qoff);
    }

    // persistent accumulators (complete O for this warp's 16 rows)
    float acc2[8][4];
    #pragma unroll
    for (int i = 0; i < 8; i++) {
        acc2[i][0] = 0.f; acc2[i][1] = 0.f; acc2[i][2] = 0.f; acc2[i][3] = 0.f;
    }
    float rs0 = 0.f, rs1 = 0.f;

    // ================= stream keys: 8 chunks of 32, triple-buffered (depth 2) =================
    for (int c = 0; c < NCH; c++) {
        const int p = c % 3;
        const uint32_t sKH = smb + OFF_BUF + p * BUF_STRIDE;
        const uint32_t sVH = sKH + V_OFF;

        CP_WAIT1();          // pending = {c, c+1}; returns when chunk c landed
        __syncthreads();     // visible to all; buffer (c+2)%3 consumed at iter c-1

        issue_chunk(c + 2, (c + 2) % 3);   // overlaps compute below

        // ---- GEMM1 chunk: S[16 x 32] per warp, Q in regs, K single fp16 ----
        float acc[4][4];
        #pragma unroll
        for (int i = 0; i < 4; i++) {
            acc[i][0]=0.f; acc[i][1]=0.f; acc[i][2]=0.f; acc[i][3]=0.f;
        }
        #pragma unroll
        for (int kt = 0; kt < 4; kt++) {
            #pragma unroll
            for (int s = 0; s < 2; s++) {
                const uint32_t koff = sw128((uint32_t)((s * 16 + b_nrow) * 128 + kt * 32 + b_seg));
                unsigned bh[4];
                ldsm_x4(bh[0], bh[1], bh[2], bh[3], sKH + koff);
                mma_f16(acc[2*s],   qfrag[kt], bh[0], bh[1]);
                mma_f16(acc[2*s+1], qfrag[kt], bh[2], bh[3]);
            }
        }

        // ---- softmax chunk (exp2; no max subtraction; masks handle pads) ----
        unsigned pe[4][2];   // P fp16
        #pragma unroll
        for (int nt = 0; nt < 4; nt++) {
            int kidx = c * CHK + nt * 8 + tig * 2;
            float m0 = maskv[kidx], m1 = maskv[kidx + 1];
            float e0 = exp2f(acc[nt][0] + m0);
            float e1 = exp2f(acc[nt][1] + m1);
            float e2 = exp2f(acc[nt][2] + m0);
            float e3 = exp2f(acc[nt][3] + m1);
            rs0 += e0 + e1;
            rs1 += e2 + e3;
            pe[nt][0] = pack2h(__float2half_rn(e0), __float2half_rn(e1));
            pe[nt][1] = pack2h(__float2half_rn(e2), __float2half_rn(e3));
        }

        // ---- GEMM2 chunk: accumulate O over all 32 chunk keys (P single fp16) ----
        #pragma unroll
        for (int s = 0; s < 2; s++) {
            unsigned ah[4] = { pe[2*s][0], pe[2*s][1], pe[2*s+1][0], pe[2*s+1][1] };
            #pragma unroll
            for (int pp = 0; pp < 4; pp++) {
                const uint32_t voff = sw128((uint32_t)((s * 16 + v_krow) * 128 + pp * 32 + v_seg));
                unsigned bh[4];
                ldsm_x4_t(bh[0], bh[1], bh[2], bh[3], sVH + voff);
                mma_f16(acc2[2*pp],   ah, bh[0], bh[1]);
                mma_f16(acc2[2*pp+1], ah, bh[2], bh[3]);
            }
        }
    }

    // ---- row-sum reduce (pure shfl; warp owns all keys for its rows) ----
    rs0 += __shfl_xor_sync(0xffffffffu, rs0, 1);
    rs0 += __shfl_xor_sync(0xffffffffu, rs0, 2);
    rs1 += __shfl_xor_sync(0xffffffffu, rs1, 1);
    rs1 += __shfl_xor_sync(0xffffffffu, rs1, 2);
    const float inv0 = 1.0f / rs0;
    const float inv1 = 1.0f / rs1;

    // ---- epilogue: direct normalized store (no cross-warp reduce) ----
    float* obase = out + ((size_t)nh * T_SEQ + (size_t)b * HALF) * D;
    #pragma unroll
    for (int nt = 0; nt < 8; nt++) {
        int cc = nt * 8 + tig * 2;
        float2 o0 = make_float2(acc2[nt][0] * inv0, acc2[nt][1] * inv0);
        float2 o1 = make_float2(acc2[nt][2] * inv1, acc2[nt][3] * inv1);
        *reinterpret_cast<float2*>(obase + (row0 + gr) * D + cc)     = o0;
        *reinterpret_cast<float2*>(obase + (row0 + gr + 8) * D + cc) = o1;
    }
}

extern "C" void kernel_launch(void* const* d_in, const int* in_sizes, int n_in,
                              void* d_out, int out_size) {
    const float* q   = (const float*)d_in[0];
    const float* k   = (const float*)d_in[1];
    const float* v   = (const float*)d_in[2];
    const float* am  = (const float*)d_in[3];
    const float* gk  = (const float*)d_in[4];
    const float* gv  = (const float*)d_in[5];
    const float* gmk = (const float*)d_in[6];
    float* out = (float*)d_out;

    // preprocessing: convert K/V to fp16 persistent arrays
    const size_t total4 = MAIN4 + G4;
    const int pgrid = (int)((total4 + 255) / 256);
    prep_kernel<<<pgrid, 256>>>(k, v, gk, gv);

    cudaFuncSetAttribute(bla_kernel, cudaFuncAttributeMaxDynamicSharedMemorySize, SMEM_BYTES);
    dim3 grid(NB, NHEAD, NBATCH);   // b fastest -> adjacent CTAs share K/V window in L2
    bla_kernel<<<grid, 128, SMEM_BYTES>>>(q, am, gmk, out);
}